// round 10
// baseline (speedup 1.0000x reference)
#include <cuda_runtime.h>
#include <cuda_bf16.h>
#include <mma.h>
#include <cstdint>

using namespace nvcuda;

#define Bb 8
#define Cc 512
#define Nn 256
#define Tt 32
#define Pp 2048   // B*N
#define Mm 2048   // 4*C
#define Kk 512    // C

#define BM 128
#define BN 256
#define BK 32
#define NKIT (Kk / BK)   // 16
#define NTHR 256         // 8 warps: 2 (M) x 4 (N), 64x64 warp tiles
#define LDA 40           // 32 + 8 pad (bf16)
#define LDB 264          // 256 + 8 pad (bf16)
#define LDZ 260          // fp32 Z pitch (mult of 4)

#define SZ_A (BM * LDA)                   // 5120 bf16
#define SZ_B (BK * LDB)                   // 8448 bf16
#define BUF_ELEMS (2 * SZ_A + 2 * SZ_B)   // 27136 bf16 per stage
#define SMEM_BYTES (3 * BUF_ELEMS * 2)    // 162816 B (3-stage; Zs 133120B aliases)

// ------------ device scratch (no allocs allowed) ------------
__device__ __align__(16) __nv_bfloat16 g_XtH[(size_t)Tt * Kk * Pp]; // [t][k][p]
__device__ __align__(16) __nv_bfloat16 g_XtL[(size_t)Tt * Kk * Pp];
__device__ __align__(16) float         g_XP[(size_t)Tt * Mm * Pp];  // [t][m][p], m=4c+g
__device__ __align__(16) float         g_Hseq[(size_t)Tt * Cc * Pp];// [t][c][p]
__device__ __align__(16) __nv_bfloat16 g_WxH[Mm * Kk], g_WxL[Mm * Kk]; // rows m=4c+g
__device__ __align__(16) __nv_bfloat16 g_WhH[Mm * Kk], g_WhL[Mm * Kk];
__device__ __align__(16) __nv_bfloat16 g_HH[2][Kk * Pp], g_HL[2][Kk * Pp]; // H: [k][p]
__device__ __align__(16) float         g_Cell[Cc * Pp];

// ------------ cp.async helpers ------------
__device__ __forceinline__ void cp16(void* dst, const void* src) {
    unsigned int d = (unsigned int)__cvta_generic_to_shared(dst);
    asm volatile("cp.async.cg.shared.global [%0], [%1], 16;\n" :: "r"(d), "l"(src));
}
#define CP_COMMIT() asm volatile("cp.async.commit_group;\n" ::)

__device__ __forceinline__ void bf16_split(float v, __nv_bfloat16& h, __nv_bfloat16& l) {
    h = __float2bfloat16(v);
    l = __float2bfloat16(v - __bfloat162float(h));
}

// ------------ setup kernels ------------
__global__ void init_state() {
    int i = blockIdx.x * blockDim.x + threadIdx.x;
    if (i < Kk * Pp) {
        __nv_bfloat16 z = __float2bfloat16(0.f);
        g_HH[0][i] = z; g_HH[1][i] = z;
        g_HL[0][i] = z; g_HL[1][i] = z;
        g_Cell[i] = 0.f;
    }
}

__global__ void split_weights(const float* __restrict__ Wx, const float* __restrict__ Wh) {
    int idx = blockIdx.x * blockDim.x + threadIdx.x;
    if (idx >= 4 * Cc * Cc) return;
    int g = idx >> 18;
    int rem = idx & ((1 << 18) - 1);
    int c = rem >> 9;
    int k = rem & 511;
    int m = (c << 2) | g;
    __nv_bfloat16 h, l;
    bf16_split(Wx[idx], h, l);
    g_WxH[m * Kk + k] = h; g_WxL[m * Kk + k] = l;
    bf16_split(Wh[idx], h, l);
    g_WhH[m * Kk + k] = h; g_WhL[m * Kk + k] = l;
}

// x (B,C,N,T) -> Xt hi/lo [t][c][b*N+n]
__global__ void transpose_split_x(const float* __restrict__ x) {
    __shared__ float tile[32][33];
    int bid   = blockIdx.x;
    int ntile = bid & 7;
    int bc    = bid >> 3;
    int c     = bc & (Cc - 1);
    int b     = bc >> 9;
    int tid = threadIdx.x;
    int tr = tid >> 5, tc = tid & 31;
    const float* src = x + ((size_t)(b * Cc + c) * Nn + ntile * 32) * Tt;
#pragma unroll
    for (int r0 = 0; r0 < 32; r0 += 8)
        tile[r0 + tr][tc] = src[(size_t)(r0 + tr) * Tt + tc];
    __syncthreads();
#pragma unroll
    for (int r0 = 0; r0 < 32; r0 += 8) {
        int t = r0 + tr;
        float v = tile[tc][t];
        __nv_bfloat16 h, l;
        bf16_split(v, h, l);
        size_t o = ((size_t)t * Kk + c) * Pp + b * Nn + ntile * 32 + tc;
        g_XtH[o] = h; g_XtL[o] = l;
    }
}

// g_Hseq[t][c][b*N+n] -> out (B,C,N,T)
__global__ void transpose_out(float* __restrict__ out) {
    __shared__ float tile[32][33];
    int bid   = blockIdx.x;
    int ntile = bid & 7;
    int bc    = bid >> 3;
    int c     = bc & (Cc - 1);
    int b     = bc >> 9;
    int tid = threadIdx.x;
    int tr = tid >> 5, tc = tid & 31;
#pragma unroll
    for (int r0 = 0; r0 < 32; r0 += 8) {
        int t = r0 + tr;
        tile[tc][t] = g_Hseq[((size_t)t * Cc + c) * Pp + b * Nn + ntile * 32 + tc];
    }
    __syncthreads();
    float* dst = out + ((size_t)(b * Cc + c) * Nn + ntile * 32) * Tt;
#pragma unroll
    for (int r0 = 0; r0 < 32; r0 += 8) {
        int n = r0 + tr;
        dst[(size_t)n * Tt + tc] = tile[n][tc];
    }
}

// ---- unified core: 128x256 block tile, 2x4 warps, 64x64 warp tiles, 3-stage ----
struct AccT {
    wmma::fragment<wmma::accumulator, 16, 16, 16, float> a[4][4];
};

__device__ __forceinline__ void gemm_core(
    const __nv_bfloat16* __restrict__ AH, const __nv_bfloat16* __restrict__ AL,
    const __nv_bfloat16* __restrict__ BH, const __nv_bfloat16* __restrict__ BL,
    __nv_bfloat16* sm, int tid, int wm, int wn, AccT& acc)
{
#pragma unroll
    for (int i = 0; i < 4; i++)
#pragma unroll
        for (int j = 0; j < 4; j++) wmma::fill_fragment(acc.a[i][j], 0.f);

    auto load_tiles = [&](int buf, int k0) {
        __nv_bfloat16* base = sm + buf * BUF_ELEMS;
        __nv_bfloat16* asH = base;
        __nv_bfloat16* asL = base + SZ_A;
        __nv_bfloat16* bsH = base + 2 * SZ_A;
        __nv_bfloat16* bsL = base + 2 * SZ_A + SZ_B;
#pragma unroll
        for (int it = 0; it < 2; ++it) {          // A: 128 rows x 4 chunks of 8 (hi+lo)
            int idx = tid + it * NTHR;
            int row = idx >> 2, q = idx & 3;
            cp16(asH + row * LDA + q * 8, AH + (size_t)row * Kk + k0 + q * 8);
            cp16(asL + row * LDA + q * 8, AL + (size_t)row * Kk + k0 + q * 8);
        }
#pragma unroll
        for (int it = 0; it < 4; ++it) {          // B: 32 k-rows x 32 chunks of 8 (hi+lo)
            int idx = tid + it * NTHR;
            int kk = idx >> 5, q = idx & 31;
            cp16(bsH + kk * LDB + q * 8, BH + (size_t)(k0 + kk) * Pp + q * 8);
            cp16(bsL + kk * LDB + q * 8, BL + (size_t)(k0 + kk) * Pp + q * 8);
        }
        CP_COMMIT();
    };

    auto compute = [&](int buf) {
        __nv_bfloat16* base = sm + buf * BUF_ELEMS;
        __nv_bfloat16* asH = base;
        __nv_bfloat16* asL = base + SZ_A;
        __nv_bfloat16* bsH = base + 2 * SZ_A;
        __nv_bfloat16* bsL = base + 2 * SZ_A + SZ_B;
#pragma unroll
        for (int kk = 0; kk < BK; kk += 16) {
            wmma::fragment<wmma::matrix_a, 16, 16, 16, __nv_bfloat16, wmma::row_major> ah[4], al[4];
#pragma unroll
            for (int i = 0; i < 4; i++) {
                wmma::load_matrix_sync(ah[i], asH + (wm * 64 + i * 16) * LDA + kk, LDA);
                wmma::load_matrix_sync(al[i], asL + (wm * 64 + i * 16) * LDA + kk, LDA);
            }
#pragma unroll
            for (int j = 0; j < 4; j++) {
                wmma::fragment<wmma::matrix_b, 16, 16, 16, __nv_bfloat16, wmma::row_major> bh, bl;
                wmma::load_matrix_sync(bh, bsH + kk * LDB + wn * 64 + j * 16, LDB);
                wmma::load_matrix_sync(bl, bsL + kk * LDB + wn * 64 + j * 16, LDB);
#pragma unroll
                for (int i = 0; i < 4; i++) wmma::mma_sync(acc.a[i][j], ah[i], bh, acc.a[i][j]);
#pragma unroll
                for (int i = 0; i < 4; i++) wmma::mma_sync(acc.a[i][j], al[i], bh, acc.a[i][j]);
#pragma unroll
                for (int i = 0; i < 4; i++) wmma::mma_sync(acc.a[i][j], ah[i], bl, acc.a[i][j]);
            }
        }
    };

    load_tiles(0, 0);
    load_tiles(1, BK);
#pragma unroll 1
    for (int i = 0; i < NKIT; ++i) {
        asm volatile("cp.async.wait_group 1;\n" ::);
        __syncthreads();
        if (i + 2 < NKIT) load_tiles((i + 2) % 3, (i + 2) * BK);
        compute(i % 3);
    }
}

// ------------ XP = Wx @ Xt ------------
__global__ __launch_bounds__(NTHR, 1) void xp_gemm() {
    extern __shared__ char smraw[];
    __nv_bfloat16* sm = reinterpret_cast<__nv_bfloat16*>(smraw);

    int m0 = blockIdx.x * BM;          // fast dim: m-tiles share B tile via L2
    int colTile = blockIdx.y;          // t (5b) x ptile (3b)
    int t  = colTile >> 3;
    int p0 = (colTile & 7) * BN;

    int tid    = threadIdx.x;
    int warpId = tid >> 5;
    int wm = warpId & 1;
    int wn = warpId >> 1;

    AccT acc;
    gemm_core(g_WxH + (size_t)m0 * Kk, g_WxL + (size_t)m0 * Kk,
              g_XtH + (size_t)t * Kk * Pp + p0, g_XtL + (size_t)t * Kk * Pp + p0,
              sm, tid, wm, wn, acc);

    float* XPbase = g_XP + (size_t)t * Mm * Pp + (size_t)m0 * Pp + p0;
#pragma unroll
    for (int i = 0; i < 4; i++)
#pragma unroll
        for (int j = 0; j < 4; j++)
            wmma::store_matrix_sync(XPbase + (size_t)(wm * 64 + i * 16) * Pp + wn * 64 + j * 16,
                                    acc.a[i][j], Pp, wmma::mem_row_major);
}

// ------------ one LSTM step ------------
__global__ __launch_bounds__(NTHR, 1) void lstm_step(const float* __restrict__ bx,
                                                     const float* __restrict__ bh,
                                                     int t) {
    extern __shared__ char smraw[];
    __nv_bfloat16* sm = reinterpret_cast<__nv_bfloat16*>(smraw);
    float* Zs = reinterpret_cast<float*>(smraw);   // alias after GEMM completes

    int p0 = blockIdx.x * BN;
    int m0 = blockIdx.y * BM;

    int tid    = threadIdx.x;
    int warpId = tid >> 5;
    int wm = warpId & 1;
    int wn = warpId >> 1;

    AccT acc;
    gemm_core(g_WhH + (size_t)m0 * Kk, g_WhL + (size_t)m0 * Kk,
              g_HH[t & 1] + p0, g_HL[t & 1] + p0,
              sm, tid, wm, wn, acc);

    __syncthreads();   // all warps done reading GEMM buffers before alias
#pragma unroll
    for (int i = 0; i < 4; i++)
#pragma unroll
        for (int j = 0; j < 4; j++)
            wmma::store_matrix_sync(Zs + (wm * 64 + i * 16) * LDZ + wn * 64 + j * 16,
                                    acc.a[i][j], LDZ, wmma::mem_row_major);
    __syncthreads();

    __nv_bfloat16* HoutH = g_HH[(t + 1) & 1];
    __nv_bfloat16* HoutL = g_HL[(t + 1) & 1];
    const float* xpb = g_XP + (size_t)t * Mm * Pp;
#pragma unroll
    for (int it = 0; it < 32; it++) {
        int idx = tid + it * NTHR;       // 0..8191
        int cl = idx >> 8;               // 0..31 channel within tile
        int pl = idx & 255;
        int c = (m0 >> 2) + cl;
        int p = p0 + pl;
        size_t xr = (size_t)(c * 4) * Pp + p;

        float zi = Zs[(4 * cl + 0) * LDZ + pl] + xpb[xr]          + bx[c]          + bh[c];
        float zf = Zs[(4 * cl + 1) * LDZ + pl] + xpb[xr + Pp]     + bx[Cc + c]     + bh[Cc + c];
        float zo = Zs[(4 * cl + 2) * LDZ + pl] + xpb[xr + 2 * Pp] + bx[2 * Cc + c] + bh[2 * Cc + c];
        float zg = Zs[(4 * cl + 3) * LDZ + pl] + xpb[xr + 3 * Pp] + bx[3 * Cc + c] + bh[3 * Cc + c];

        float ig = 1.f / (1.f + __expf(-zi));
        float fg = 1.f / (1.f + __expf(-zf));
        float og = 1.f / (1.f + __expf(-zo));
        float gg = tanhf(zg);

        float cp = g_Cell[c * Pp + p];
        float cn = fg * cp + ig * gg;
        g_Cell[c * Pp + p] = cn;
        float h = og * tanhf(cn);

        __nv_bfloat16 hh, hl;
        bf16_split(h, hh, hl);
        HoutH[c * Pp + p] = hh;
        HoutL[c * Pp + p] = hl;

        g_Hseq[((size_t)t * Cc + c) * Pp + p] = h;
    }
}

extern "C" void kernel_launch(void* const* d_in, const int* in_sizes, int n_in,
                              void* d_out, int out_size) {
    const float* x  = (const float*)d_in[0];
    const float* Wx = (const float*)d_in[1];
    const float* bx = (const float*)d_in[2];
    const float* Wh = (const float*)d_in[3];
    const float* bh = (const float*)d_in[4];
    float* out = (float*)d_out;

    cudaFuncSetAttribute(xp_gemm,   cudaFuncAttributeMaxDynamicSharedMemorySize, SMEM_BYTES);
    cudaFuncSetAttribute(lstm_step, cudaFuncAttributeMaxDynamicSharedMemorySize, SMEM_BYTES);

    init_state<<<(Kk * Pp + 255) / 256, 256>>>();
    split_weights<<<(4 * Cc * Cc + 255) / 256, 256>>>(Wx, Wh);
    transpose_split_x<<<Bb * Cc * (Nn / 32), 256>>>(x);
    xp_gemm<<<dim3(Mm / BM, Tt * (Pp / BN)), NTHR, SMEM_BYTES>>>();
    for (int t = 0; t < Tt; t++)
        lstm_step<<<dim3(Pp / BN, Mm / BM), NTHR, SMEM_BYTES>>>(bx, bh, t);
    transpose_out<<<Bb * Cc * (Nn / 32), 256>>>(out);
}

// round 11
// speedup vs baseline: 1.0677x; 1.0677x over previous
#include <cuda_runtime.h>
#include <cuda_bf16.h>
#include <mma.h>
#include <cstdint>

using namespace nvcuda;

#define Bb 8
#define Cc 512
#define Nn 256
#define Tt 32
#define Pp 2048   // B*N
#define Mm 2048   // 4*C
#define Kk 512    // C
#define K1 1024   // concat K: [Wx | Wh]

#define BM 128
#define BN 128
#define BK 32
#define NKIT1 (K1 / BK)  // 32
#define LDA 40           // 32 + 8 pad (bf16)
#define LDB 136          // 128 + 8 pad
#define LDZ 132          // fp32 staging pitch

#define SZ_A (BM * LDA)              // 5120 bf16
#define SZ_B (BK * LDB)              // 4352 bf16
#define BUF_ELEMS (2 * SZ_A + 2 * SZ_B)   // 18944 bf16 per stage
#define SMEM_ST (2 * BUF_ELEMS * 2)       // 75776 B (2-stage)

// ------------ device scratch (no allocs allowed) ------------
__device__ __align__(16) __nv_bfloat16 g_XtH[(size_t)Tt * Kk * Pp]; // [t][k][p]
__device__ __align__(16) __nv_bfloat16 g_XtL[(size_t)Tt * Kk * Pp];
__device__ __align__(16) float         g_Hseq[(size_t)Tt * Cc * Pp];// [t][c][p]
__device__ __align__(16) __nv_bfloat16 g_WcH[(size_t)Mm * K1];      // [m][k0..511]=Wx, [512..1023]=Wh
__device__ __align__(16) __nv_bfloat16 g_WcL[(size_t)Mm * K1];
__device__ __align__(16) __nv_bfloat16 g_HH[2][Kk * Pp], g_HL[2][Kk * Pp]; // H: [k][p]
__device__ __align__(16) float         g_Cell[Cc * Pp];
__device__ __align__(16) float         g_bias[Mm];                  // bx+bh, index g*C+c

// ------------ cp.async helpers ------------
__device__ __forceinline__ void cp16(void* dst, const void* src) {
    unsigned int d = (unsigned int)__cvta_generic_to_shared(dst);
    asm volatile("cp.async.cg.shared.global [%0], [%1], 16;\n" :: "r"(d), "l"(src));
}
#define CP_COMMIT() asm volatile("cp.async.commit_group;\n" ::)
#define CP_WAIT1()  asm volatile("cp.async.wait_group 1;\n" ::)
#define CP_WAIT0()  asm volatile("cp.async.wait_group 0;\n" ::)

__device__ __forceinline__ void bf16_split(float v, __nv_bfloat16& h, __nv_bfloat16& l) {
    h = __float2bfloat16(v);
    l = __float2bfloat16(v - __bfloat162float(h));
}

// ------------ setup kernels ------------
__global__ void init_state() {
    int i = blockIdx.x * blockDim.x + threadIdx.x;
    if (i < Kk * Pp) {
        __nv_bfloat16 z = __float2bfloat16(0.f);
        g_HH[0][i] = z; g_HH[1][i] = z;
        g_HL[0][i] = z; g_HL[1][i] = z;
        g_Cell[i] = 0.f;
    }
}

// Wx,Wh (4,C,C) fp32 -> combined bf16 hi/lo [m][k] with m=4c+g, k-concat; plus bias sum
__global__ void split_weights(const float* __restrict__ Wx, const float* __restrict__ Wh,
                              const float* __restrict__ bx, const float* __restrict__ bh) {
    int idx = blockIdx.x * blockDim.x + threadIdx.x;
    if (idx >= 4 * Cc * Cc) return;
    int g = idx >> 18;
    int rem = idx & ((1 << 18) - 1);
    int c = rem >> 9;
    int k = rem & 511;
    int m = (c << 2) | g;
    __nv_bfloat16 h, l;
    bf16_split(Wx[idx], h, l);
    g_WcH[(size_t)m * K1 + k] = h; g_WcL[(size_t)m * K1 + k] = l;
    bf16_split(Wh[idx], h, l);
    g_WcH[(size_t)m * K1 + Kk + k] = h; g_WcL[(size_t)m * K1 + Kk + k] = l;
    if (idx < 4 * Cc) g_bias[idx] = bx[idx] + bh[idx];   // index g*C+c
}

// x (B,C,N,T) -> Xt hi/lo [t][c][b*N+n]
__global__ void transpose_split_x(const float* __restrict__ x) {
    __shared__ float tile[32][33];
    int bid   = blockIdx.x;
    int ntile = bid & 7;
    int bc    = bid >> 3;
    int c     = bc & (Cc - 1);
    int b     = bc >> 9;
    int tid = threadIdx.x;
    int tr = tid >> 5, tc = tid & 31;
    const float* src = x + ((size_t)(b * Cc + c) * Nn + ntile * 32) * Tt;
#pragma unroll
    for (int r0 = 0; r0 < 32; r0 += 8)
        tile[r0 + tr][tc] = src[(size_t)(r0 + tr) * Tt + tc];
    __syncthreads();
#pragma unroll
    for (int r0 = 0; r0 < 32; r0 += 8) {
        int t = r0 + tr;
        float v = tile[tc][t];
        __nv_bfloat16 h, l;
        bf16_split(v, h, l);
        size_t o = ((size_t)t * Kk + c) * Pp + b * Nn + ntile * 32 + tc;
        g_XtH[o] = h; g_XtL[o] = l;
    }
}

// g_Hseq[t][c][b*N+n] -> out (B,C,N,T)
__global__ void transpose_out(float* __restrict__ out) {
    __shared__ float tile[32][33];
    int bid   = blockIdx.x;
    int ntile = bid & 7;
    int bc    = bid >> 3;
    int c     = bc & (Cc - 1);
    int b     = bc >> 9;
    int tid = threadIdx.x;
    int tr = tid >> 5, tc = tid & 31;
#pragma unroll
    for (int r0 = 0; r0 < 32; r0 += 8) {
        int t = r0 + tr;
        tile[tc][t] = g_Hseq[((size_t)t * Cc + c) * Pp + b * Nn + ntile * 32 + tc];
    }
    __syncthreads();
    float* dst = out + ((size_t)(b * Cc + c) * Nn + ntile * 32) * Tt;
#pragma unroll
    for (int r0 = 0; r0 < 32; r0 += 8) {
        int n = r0 + tr;
        dst[(size_t)n * Tt + tc] = tile[n][tc];
    }
}

// ---- fused step GEMM core: 128x128 tile, 4x2 warps (32x64), K=1024, 2-stage ----
struct AccST {
    wmma::fragment<wmma::accumulator, 16, 16, 16, float> a[2][4];
};

// B row source for global k row: k<512 -> Xt[t], else H
__global__ __launch_bounds__(256, 2) void lstm_step(float* __restrict__ dummy, int t) {
    extern __shared__ char smraw[];
    __nv_bfloat16* sm = reinterpret_cast<__nv_bfloat16*>(smraw);
    float* Zs = reinterpret_cast<float*>(smraw);   // alias after GEMM

    int p0 = blockIdx.x * BN;
    int m0 = blockIdx.y * BM;

    int tid    = threadIdx.x;
    int warpId = tid >> 5;
    int wm = warpId & 3;
    int wn = warpId >> 2;

    const __nv_bfloat16* AH = g_WcH + (size_t)m0 * K1;
    const __nv_bfloat16* AL = g_WcL + (size_t)m0 * K1;
    const __nv_bfloat16* XtHb = g_XtH + (size_t)t * Kk * Pp + p0;
    const __nv_bfloat16* XtLb = g_XtL + (size_t)t * Kk * Pp + p0;
    const __nv_bfloat16* HHb = g_HH[t & 1] + p0;
    const __nv_bfloat16* HLb = g_HL[t & 1] + p0;

    AccST acc;
#pragma unroll
    for (int i = 0; i < 2; i++)
#pragma unroll
        for (int j = 0; j < 4; j++) wmma::fill_fragment(acc.a[i][j], 0.f);

    auto load_tiles = [&](int buf, int k0) {
        __nv_bfloat16* base = sm + buf * BUF_ELEMS;
        __nv_bfloat16* asH = base;
        __nv_bfloat16* asL = base + SZ_A;
        __nv_bfloat16* bsH = base + 2 * SZ_A;
        __nv_bfloat16* bsL = base + 2 * SZ_A + SZ_B;
#pragma unroll
        for (int it = 0; it < 2; ++it) {
            int idx = tid + it * 256;
            int row = idx >> 2, q = idx & 3;
            cp16(asH + row * LDA + q * 8, AH + (size_t)row * K1 + k0 + q * 8);
            cp16(asL + row * LDA + q * 8, AL + (size_t)row * K1 + k0 + q * 8);
        }
        const __nv_bfloat16* BH = (k0 < Kk) ? XtHb + (size_t)k0 * Pp : HHb + (size_t)(k0 - Kk) * Pp;
        const __nv_bfloat16* BL = (k0 < Kk) ? XtLb + (size_t)k0 * Pp : HLb + (size_t)(k0 - Kk) * Pp;
#pragma unroll
        for (int it = 0; it < 2; ++it) {
            int idx = tid + it * 256;
            int kk = idx >> 4, q = idx & 15;
            cp16(bsH + kk * LDB + q * 8, BH + (size_t)kk * Pp + q * 8);
            cp16(bsL + kk * LDB + q * 8, BL + (size_t)kk * Pp + q * 8);
        }
        CP_COMMIT();
    };

    auto compute = [&](int buf) {
        __nv_bfloat16* base = sm + buf * BUF_ELEMS;
        __nv_bfloat16* asH = base;
        __nv_bfloat16* asL = base + SZ_A;
        __nv_bfloat16* bsH = base + 2 * SZ_A;
        __nv_bfloat16* bsL = base + 2 * SZ_A + SZ_B;
#pragma unroll
        for (int kk = 0; kk < BK; kk += 16) {
            wmma::fragment<wmma::matrix_a, 16, 16, 16, __nv_bfloat16, wmma::row_major> ah[2], al[2];
#pragma unroll
            for (int i = 0; i < 2; i++) {
                wmma::load_matrix_sync(ah[i], asH + (wm * 32 + i * 16) * LDA + kk, LDA);
                wmma::load_matrix_sync(al[i], asL + (wm * 32 + i * 16) * LDA + kk, LDA);
            }
#pragma unroll
            for (int j = 0; j < 4; j++) {
                wmma::fragment<wmma::matrix_b, 16, 16, 16, __nv_bfloat16, wmma::row_major> bh, bl;
                wmma::load_matrix_sync(bh, bsH + kk * LDB + wn * 64 + j * 16, LDB);
                wmma::load_matrix_sync(bl, bsL + kk * LDB + wn * 64 + j * 16, LDB);
#pragma unroll
                for (int i = 0; i < 2; i++) {
                    wmma::mma_sync(acc.a[i][j], ah[i], bh, acc.a[i][j]);
                    wmma::mma_sync(acc.a[i][j], al[i], bh, acc.a[i][j]);
                    wmma::mma_sync(acc.a[i][j], ah[i], bl, acc.a[i][j]);
                }
            }
        }
    };

    load_tiles(0, 0);
#pragma unroll 1
    for (int i = 0; i < NKIT1; ++i) {
        if (i + 1 < NKIT1) { load_tiles((i + 1) & 1, (i + 1) * BK); CP_WAIT1(); }
        else               { CP_WAIT0(); }
        __syncthreads();
        compute(i & 1);
        __syncthreads();
    }

    // epilogue: stage Z, gates, state update
#pragma unroll
    for (int i = 0; i < 2; i++)
#pragma unroll
        for (int j = 0; j < 4; j++)
            wmma::store_matrix_sync(Zs + (wm * 32 + i * 16) * LDZ + wn * 64 + j * 16,
                                    acc.a[i][j], LDZ, wmma::mem_row_major);
    __syncthreads();

    __nv_bfloat16* HoutH = g_HH[(t + 1) & 1];
    __nv_bfloat16* HoutL = g_HL[(t + 1) & 1];
#pragma unroll
    for (int it = 0; it < 16; it++) {
        int idx = tid + it * 256;
        int cl = idx >> 7;
        int pl = idx & 127;
        int c = (m0 >> 2) + cl;
        int p = p0 + pl;

        float zi = Zs[(4 * cl + 0) * LDZ + pl] + g_bias[c];
        float zf = Zs[(4 * cl + 1) * LDZ + pl] + g_bias[Cc + c];
        float zo = Zs[(4 * cl + 2) * LDZ + pl] + g_bias[2 * Cc + c];
        float zg = Zs[(4 * cl + 3) * LDZ + pl] + g_bias[3 * Cc + c];

        float ig = 1.f / (1.f + __expf(-zi));
        float fg = 1.f / (1.f + __expf(-zf));
        float og = 1.f / (1.f + __expf(-zo));
        float gg = tanhf(zg);

        float cp = g_Cell[c * Pp + p];
        float cn = fg * cp + ig * gg;
        g_Cell[c * Pp + p] = cn;
        float h = og * tanhf(cn);

        __nv_bfloat16 hh, hl;
        bf16_split(h, hh, hl);
        HoutH[c * Pp + p] = hh;
        HoutL[c * Pp + p] = hl;

        g_Hseq[((size_t)t * Cc + c) * Pp + p] = h;
    }
}

extern "C" void kernel_launch(void* const* d_in, const int* in_sizes, int n_in,
                              void* d_out, int out_size) {
    const float* x  = (const float*)d_in[0];
    const float* Wx = (const float*)d_in[1];
    const float* bx = (const float*)d_in[2];
    const float* Wh = (const float*)d_in[3];
    const float* bh = (const float*)d_in[4];
    float* out = (float*)d_out;

    cudaFuncSetAttribute(lstm_step, cudaFuncAttributeMaxDynamicSharedMemorySize, SMEM_ST);

    init_state<<<(Kk * Pp + 255) / 256, 256>>>();
    split_weights<<<(4 * Cc * Cc + 255) / 256, 256>>>(Wx, Wh, bx, bh);
    transpose_split_x<<<Bb * Cc * (Nn / 32), 256>>>(x);
    for (int t = 0; t < Tt; t++)
        lstm_step<<<dim3(16, 16), 256, SMEM_ST>>>(out, t);
    transpose_out<<<Bb * Cc * (Nn / 32), 256>>>(out);
}

// round 12
// speedup vs baseline: 1.1971x; 1.1212x over previous
#include <cuda_runtime.h>
#include <cuda_bf16.h>
#include <mma.h>
#include <cstdint>

using namespace nvcuda;

#define Bb 8
#define Cc 512
#define Nn 256
#define Tt 32
#define Pp 2048   // B*N
#define Mm 2048   // 4*C
#define Kk 512    // C

#define BM 128
#define BN 128
#define BK 32
#define NKIT (Kk / BK)   // 16
#define LDA 40           // 32 + 8 pad (bf16)
#define LDB 136          // 128 + 8 pad
#define LDZ 132          // fp32 staging pitch

#define SZ_A (BM * LDA)              // 5120 bf16
#define SZ_B (BK * LDB)              // 4352 bf16
#define BUF_ELEMS (2 * SZ_A + 2 * SZ_B)   // 18944 bf16 per stage
#define SMEM_XP (3 * BUF_ELEMS * 2)       // 113664 B (3-stage)
#define SMEM_ST (2 * BUF_ELEMS * 2)       // 75776 B (2-stage)

// ------------ device scratch (no allocs allowed) ------------
__device__ __align__(16) __nv_bfloat16 g_XtH[(size_t)Tt * Kk * Pp]; // [t][k][p]
__device__ __align__(16) __nv_bfloat16 g_XtL[(size_t)Tt * Kk * Pp];
__device__ __align__(16) float         g_XP[(size_t)Tt * Mm * Pp];  // [t][m][p], m=4c+g
__device__ __align__(16) float         g_Hseq[(size_t)Tt * Cc * Pp];// [t][c][p]
__device__ __align__(16) __nv_bfloat16 g_WxH[Mm * Kk], g_WxL[Mm * Kk]; // rows m=4c+g
__device__ __align__(16) __nv_bfloat16 g_WhH[Mm * Kk], g_WhL[Mm * Kk];
__device__ __align__(16) __nv_bfloat16 g_HH[2][Kk * Pp], g_HL[2][Kk * Pp]; // H: [k][p]
__device__ __align__(16) float         g_Cell[Cc * Pp];

// ------------ cp.async helpers ------------
__device__ __forceinline__ void cp16(void* dst, const void* src) {
    unsigned int d = (unsigned int)__cvta_generic_to_shared(dst);
    asm volatile("cp.async.cg.shared.global [%0], [%1], 16;\n" :: "r"(d), "l"(src));
}
#define CP_COMMIT() asm volatile("cp.async.commit_group;\n" ::)
#define CP_WAIT1()  asm volatile("cp.async.wait_group 1;\n" ::)
#define CP_WAIT0()  asm volatile("cp.async.wait_group 0;\n" ::)

__device__ __forceinline__ void bf16_split(float v, __nv_bfloat16& h, __nv_bfloat16& l) {
    h = __float2bfloat16(v);
    l = __float2bfloat16(v - __bfloat162float(h));
}

// ------------ setup kernels ------------
__global__ void init_state() {
    int i = blockIdx.x * blockDim.x + threadIdx.x;
    if (i < Kk * Pp) {
        __nv_bfloat16 z = __float2bfloat16(0.f);
        g_HH[0][i] = z; g_HH[1][i] = z;
        g_HL[0][i] = z; g_HL[1][i] = z;
        g_Cell[i] = 0.f;
    }
}

__global__ void split_weights(const float* __restrict__ Wx, const float* __restrict__ Wh) {
    int idx = blockIdx.x * blockDim.x + threadIdx.x;
    if (idx >= 4 * Cc * Cc) return;
    int g = idx >> 18;
    int rem = idx & ((1 << 18) - 1);
    int c = rem >> 9;
    int k = rem & 511;
    int m = (c << 2) | g;
    __nv_bfloat16 h, l;
    bf16_split(Wx[idx], h, l);
    g_WxH[m * Kk + k] = h; g_WxL[m * Kk + k] = l;
    bf16_split(Wh[idx], h, l);
    g_WhH[m * Kk + k] = h; g_WhL[m * Kk + k] = l;
}

// x (B,C,N,T) -> Xt hi/lo [t][c][b*N+n]
__global__ void transpose_split_x(const float* __restrict__ x) {
    __shared__ float tile[32][33];
    int bid   = blockIdx.x;
    int ntile = bid & 7;
    int bc    = bid >> 3;
    int c     = bc & (Cc - 1);
    int b     = bc >> 9;
    int tid = threadIdx.x;
    int tr = tid >> 5, tc = tid & 31;
    const float* src = x + ((size_t)(b * Cc + c) * Nn + ntile * 32) * Tt;
#pragma unroll
    for (int r0 = 0; r0 < 32; r0 += 8)
        tile[r0 + tr][tc] = src[(size_t)(r0 + tr) * Tt + tc];
    __syncthreads();
#pragma unroll
    for (int r0 = 0; r0 < 32; r0 += 8) {
        int t = r0 + tr;
        float v = tile[tc][t];
        __nv_bfloat16 h, l;
        bf16_split(v, h, l);
        size_t o = ((size_t)t * Kk + c) * Pp + b * Nn + ntile * 32 + tc;
        g_XtH[o] = h; g_XtL[o] = l;
    }
}

// g_Hseq[t][c][b*N+n] -> out (B,C,N,T)
__global__ void transpose_out(float* __restrict__ out) {
    __shared__ float tile[32][33];
    int bid   = blockIdx.x;
    int ntile = bid & 7;
    int bc    = bid >> 3;
    int c     = bc & (Cc - 1);
    int b     = bc >> 9;
    int tid = threadIdx.x;
    int tr = tid >> 5, tc = tid & 31;
#pragma unroll
    for (int r0 = 0; r0 < 32; r0 += 8) {
        int t = r0 + tr;
        tile[tc][t] = g_Hseq[((size_t)t * Cc + c) * Pp + b * Nn + ntile * 32 + tc];
    }
    __syncthreads();
    float* dst = out + ((size_t)(b * Cc + c) * Nn + ntile * 32) * Tt;
#pragma unroll
    for (int r0 = 0; r0 < 32; r0 += 8) {
        int n = r0 + tr;
        dst[(size_t)n * Tt + tc] = tile[n][tc];
    }
}

// =========== CORE A: 128 thr, 2x2 warps, 64x64 tiles, 3-stage (for xp_gemm) ===========
struct AccXP {
    wmma::fragment<wmma::accumulator, 16, 16, 16, float> a[4][4];
};

__device__ __forceinline__ void gemm_core_xp(
    const __nv_bfloat16* __restrict__ AH, const __nv_bfloat16* __restrict__ AL,
    const __nv_bfloat16* __restrict__ BH, const __nv_bfloat16* __restrict__ BL,
    __nv_bfloat16* sm, int tid, int wm, int wn, AccXP& acc)
{
#pragma unroll
    for (int i = 0; i < 4; i++)
#pragma unroll
        for (int j = 0; j < 4; j++) wmma::fill_fragment(acc.a[i][j], 0.f);

    auto load_tiles = [&](int buf, int k0) {
        __nv_bfloat16* base = sm + buf * BUF_ELEMS;
        __nv_bfloat16* asH = base;
        __nv_bfloat16* asL = base + SZ_A;
        __nv_bfloat16* bsH = base + 2 * SZ_A;
        __nv_bfloat16* bsL = base + 2 * SZ_A + SZ_B;
#pragma unroll
        for (int it = 0; it < 4; ++it) {
            int idx = tid + it * 128;
            int row = idx >> 2, q = idx & 3;
            cp16(asH + row * LDA + q * 8, AH + (size_t)row * Kk + k0 + q * 8);
            cp16(asL + row * LDA + q * 8, AL + (size_t)row * Kk + k0 + q * 8);
        }
#pragma unroll
        for (int it = 0; it < 4; ++it) {
            int idx = tid + it * 128;
            int kk = idx >> 4, q = idx & 15;
            cp16(bsH + kk * LDB + q * 8, BH + (size_t)(k0 + kk) * Pp + q * 8);
            cp16(bsL + kk * LDB + q * 8, BL + (size_t)(k0 + kk) * Pp + q * 8);
        }
        CP_COMMIT();
    };

    auto compute = [&](int buf) {
        __nv_bfloat16* base = sm + buf * BUF_ELEMS;
        __nv_bfloat16* asH = base;
        __nv_bfloat16* asL = base + SZ_A;
        __nv_bfloat16* bsH = base + 2 * SZ_A;
        __nv_bfloat16* bsL = base + 2 * SZ_A + SZ_B;
#pragma unroll
        for (int kk = 0; kk < BK; kk += 16) {
            wmma::fragment<wmma::matrix_a, 16, 16, 16, __nv_bfloat16, wmma::row_major> ah[4], al[4];
#pragma unroll
            for (int i = 0; i < 4; i++) {
                wmma::load_matrix_sync(ah[i], asH + (wm * 64 + i * 16) * LDA + kk, LDA);
                wmma::load_matrix_sync(al[i], asL + (wm * 64 + i * 16) * LDA + kk, LDA);
            }
#pragma unroll
            for (int j = 0; j < 4; j++) {
                wmma::fragment<wmma::matrix_b, 16, 16, 16, __nv_bfloat16, wmma::row_major> bh, bl;
                wmma::load_matrix_sync(bh, bsH + kk * LDB + wn * 64 + j * 16, LDB);
                wmma::load_matrix_sync(bl, bsL + kk * LDB + wn * 64 + j * 16, LDB);
#pragma unroll
                for (int i = 0; i < 4; i++) wmma::mma_sync(acc.a[i][j], ah[i], bh, acc.a[i][j]);
#pragma unroll
                for (int i = 0; i < 4; i++) wmma::mma_sync(acc.a[i][j], al[i], bh, acc.a[i][j]);
#pragma unroll
                for (int i = 0; i < 4; i++) wmma::mma_sync(acc.a[i][j], ah[i], bl, acc.a[i][j]);
            }
        }
    };

    load_tiles(0, 0);
    load_tiles(1, BK);
#pragma unroll 1
    for (int i = 0; i < NKIT; ++i) {
        asm volatile("cp.async.wait_group 1;\n" ::);
        __syncthreads();
        if (i + 2 < NKIT) load_tiles((i + 2) % 3, (i + 2) * BK);
        compute(i % 3);
    }
}

__global__ __launch_bounds__(128, 2) void xp_gemm() {
    extern __shared__ char smraw[];
    __nv_bfloat16* sm = reinterpret_cast<__nv_bfloat16*>(smraw);

    int m0 = blockIdx.x * BM;          // fast dim: m-tiles share B tile via L2
    int colTile = blockIdx.y;
    int t  = colTile >> 4;
    int p0 = (colTile & 15) * BN;

    int tid    = threadIdx.x;
    int warpId = tid >> 5;
    int wm = warpId & 1;
    int wn = warpId >> 1;

    AccXP acc;
    gemm_core_xp(g_WxH + (size_t)m0 * Kk, g_WxL + (size_t)m0 * Kk,
                 g_XtH + (size_t)t * Kk * Pp + p0, g_XtL + (size_t)t * Kk * Pp + p0,
                 sm, tid, wm, wn, acc);

    float* XPbase = g_XP + (size_t)t * Mm * Pp + (size_t)m0 * Pp + p0;
#pragma unroll
    for (int i = 0; i < 4; i++)
#pragma unroll
        for (int j = 0; j < 4; j++)
            wmma::store_matrix_sync(XPbase + (size_t)(wm * 64 + i * 16) * Pp + wn * 64 + j * 16,
                                    acc.a[i][j], Pp, wmma::mem_row_major);
}

// =========== CORE B: 256 thr, 4x2 warps, 32x64 tiles, 2-stage (for lstm_step) ===========
struct AccST {
    wmma::fragment<wmma::accumulator, 16, 16, 16, float> a[2][4];
};

__device__ __forceinline__ void gemm_core_st(
    const __nv_bfloat16* __restrict__ AH, const __nv_bfloat16* __restrict__ AL,
    const __nv_bfloat16* __restrict__ BH, const __nv_bfloat16* __restrict__ BL,
    __nv_bfloat16* sm, int tid, int wm, int wn, AccST& acc)
{
    // NOTE: acc is pre-initialized by the caller (loaded from XP tile)
    auto load_tiles = [&](int buf, int k0) {
        __nv_bfloat16* base = sm + buf * BUF_ELEMS;
        __nv_bfloat16* asH = base;
        __nv_bfloat16* asL = base + SZ_A;
        __nv_bfloat16* bsH = base + 2 * SZ_A;
        __nv_bfloat16* bsL = base + 2 * SZ_A + SZ_B;
#pragma unroll
        for (int it = 0; it < 2; ++it) {
            int idx = tid + it * 256;
            int row = idx >> 2, q = idx & 3;
            cp16(asH + row * LDA + q * 8, AH + (size_t)row * Kk + k0 + q * 8);
            cp16(asL + row * LDA + q * 8, AL + (size_t)row * Kk + k0 + q * 8);
        }
#pragma unroll
        for (int it = 0; it < 2; ++it) {
            int idx = tid + it * 256;
            int kk = idx >> 4, q = idx & 15;
            cp16(bsH + kk * LDB + q * 8, BH + (size_t)(k0 + kk) * Pp + q * 8);
            cp16(bsL + kk * LDB + q * 8, BL + (size_t)(k0 + kk) * Pp + q * 8);
        }
        CP_COMMIT();
    };

    auto compute = [&](int buf) {
        __nv_bfloat16* base = sm + buf * BUF_ELEMS;
        __nv_bfloat16* asH = base;
        __nv_bfloat16* asL = base + SZ_A;
        __nv_bfloat16* bsH = base + 2 * SZ_A;
        __nv_bfloat16* bsL = base + 2 * SZ_A + SZ_B;
#pragma unroll
        for (int kk = 0; kk < BK; kk += 16) {
            wmma::fragment<wmma::matrix_a, 16, 16, 16, __nv_bfloat16, wmma::row_major> ah[2], al[2];
#pragma unroll
            for (int i = 0; i < 2; i++) {
                wmma::load_matrix_sync(ah[i], asH + (wm * 32 + i * 16) * LDA + kk, LDA);
                wmma::load_matrix_sync(al[i], asL + (wm * 32 + i * 16) * LDA + kk, LDA);
            }
#pragma unroll
            for (int j = 0; j < 4; j++) {
                wmma::fragment<wmma::matrix_b, 16, 16, 16, __nv_bfloat16, wmma::row_major> bh, bl;
                wmma::load_matrix_sync(bh, bsH + kk * LDB + wn * 64 + j * 16, LDB);
                wmma::load_matrix_sync(bl, bsL + kk * LDB + wn * 64 + j * 16, LDB);
#pragma unroll
                for (int i = 0; i < 2; i++) {
                    wmma::mma_sync(acc.a[i][j], ah[i], bh, acc.a[i][j]);
                    wmma::mma_sync(acc.a[i][j], al[i], bh, acc.a[i][j]);
                    wmma::mma_sync(acc.a[i][j], ah[i], bl, acc.a[i][j]);
                }
            }
        }
    };

    load_tiles(0, 0);
#pragma unroll 1
    for (int i = 0; i < NKIT; ++i) {
        if (i + 1 < NKIT) { load_tiles((i + 1) & 1, (i + 1) * BK); CP_WAIT1(); }
        else              { CP_WAIT0(); }
        __syncthreads();
        compute(i & 1);
        __syncthreads();
    }
}

__global__ __launch_bounds__(256, 2) void lstm_step(const float* __restrict__ bx,
                                                    const float* __restrict__ bh,
                                                    int t) {
    extern __shared__ char smraw[];
    __nv_bfloat16* sm = reinterpret_cast<__nv_bfloat16*>(smraw);
    float* Zs = reinterpret_cast<float*>(smraw);   // alias, used after final sync

    int p0 = blockIdx.x * BN;
    int m0 = blockIdx.y * BM;

    int tid    = threadIdx.x;
    int warpId = tid >> 5;
    int wm = warpId & 3;
    int wn = warpId >> 2;

    // init accumulators from the XP tile (z = XP + Wh@H computed by MMA)
    AccST acc;
    {
        const float* XPbase = g_XP + (size_t)t * Mm * Pp + (size_t)m0 * Pp + p0;
#pragma unroll
        for (int i = 0; i < 2; i++)
#pragma unroll
            for (int j = 0; j < 4; j++)
                wmma::load_matrix_sync(acc.a[i][j],
                    XPbase + (size_t)(wm * 32 + i * 16) * Pp + wn * 64 + j * 16,
                    Pp, wmma::mem_row_major);
    }

    gemm_core_st(g_WhH + (size_t)m0 * Kk, g_WhL + (size_t)m0 * Kk,
                 g_HH[t & 1] + p0, g_HL[t & 1] + p0,
                 sm, tid, wm, wn, acc);

#pragma unroll
    for (int i = 0; i < 2; i++)
#pragma unroll
        for (int j = 0; j < 4; j++)
            wmma::store_matrix_sync(Zs + (wm * 32 + i * 16) * LDZ + wn * 64 + j * 16,
                                    acc.a[i][j], LDZ, wmma::mem_row_major);
    __syncthreads();

    __nv_bfloat16* HoutH = g_HH[(t + 1) & 1];
    __nv_bfloat16* HoutL = g_HL[(t + 1) & 1];
#pragma unroll
    for (int it = 0; it < 16; it++) {
        int idx = tid + it * 256;
        int cl = idx >> 7;
        int pl = idx & 127;
        int c = (m0 >> 2) + cl;
        int p = p0 + pl;

        float zi = Zs[(4 * cl + 0) * LDZ + pl] + bx[c]          + bh[c];
        float zf = Zs[(4 * cl + 1) * LDZ + pl] + bx[Cc + c]     + bh[Cc + c];
        float zo = Zs[(4 * cl + 2) * LDZ + pl] + bx[2 * Cc + c] + bh[2 * Cc + c];
        float zg = Zs[(4 * cl + 3) * LDZ + pl] + bx[3 * Cc + c] + bh[3 * Cc + c];

        float ig = 1.f / (1.f + __expf(-zi));
        float fg = 1.f / (1.f + __expf(-zf));
        float og = 1.f / (1.f + __expf(-zo));
        float gg = tanhf(zg);

        float cp = g_Cell[c * Pp + p];
        float cn = fg * cp + ig * gg;
        g_Cell[c * Pp + p] = cn;
        float h = og * tanhf(cn);

        __nv_bfloat16 hh, hl;
        bf16_split(h, hh, hl);
        HoutH[c * Pp + p] = hh;
        HoutL[c * Pp + p] = hl;

        g_Hseq[((size_t)t * Cc + c) * Pp + p] = h;
    }
}

extern "C" void kernel_launch(void* const* d_in, const int* in_sizes, int n_in,
                              void* d_out, int out_size) {
    const float* x  = (const float*)d_in[0];
    const float* Wx = (const float*)d_in[1];
    const float* bx = (const float*)d_in[2];
    const float* Wh = (const float*)d_in[3];
    const float* bh = (const float*)d_in[4];
    float* out = (float*)d_out;

    cudaFuncSetAttribute(xp_gemm,   cudaFuncAttributeMaxDynamicSharedMemorySize, SMEM_XP);
    cudaFuncSetAttribute(lstm_step, cudaFuncAttributeMaxDynamicSharedMemorySize, SMEM_ST);

    init_state<<<(Kk * Pp + 255) / 256, 256>>>();
    split_weights<<<(4 * Cc * Cc + 255) / 256, 256>>>(Wx, Wh);
    transpose_split_x<<<Bb * Cc * (Nn / 32), 256>>>(x);
    xp_gemm<<<dim3(16, 512), 128, SMEM_XP>>>();
    for (int t = 0; t < Tt; t++)
        lstm_step<<<dim3(16, 16), 256, SMEM_ST>>>(bx, bh, t);
    transpose_out<<<Bb * Cc * (Nn / 32), 256>>>(out);
}

// round 13
// speedup vs baseline: 1.2027x; 1.0047x over previous
#include <cuda_runtime.h>
#include <cuda_bf16.h>
#include <mma.h>
#include <cstdint>

using namespace nvcuda;

#define Bb 8
#define Cc 512
#define Nn 256
#define Tt 32
#define Pp 2048   // B*N
#define Mm 2048   // 4*C
#define Kk 512    // C

#define BM 128
#define BN 128
#define BK 32
#define NKIT (Kk / BK)   // 16
#define LDA 40           // 32 + 8 pad (bf16)
#define LDB 136          // 128 + 8 pad
#define LDZ 132          // fp32 staging pitch

#define SZ_A (BM * LDA)              // 5120 bf16
#define SZ_B (BK * LDB)              // 4352 bf16
#define BUF_ELEMS (2 * SZ_A + 2 * SZ_B)   // 18944 bf16 per stage
#define SMEM_XP (3 * BUF_ELEMS * 2)       // 113664 B (3-stage)
#define SMEM_ST (2 * BUF_ELEMS * 2)       // 75776 B (2-stage)

#define NBLK_ST 256      // persistent step grid (16 x 16 tiles); 256 <= 148*2 resident slots

// ------------ device scratch (no allocs allowed) ------------
__device__ __align__(16) __nv_bfloat16 g_XtH[(size_t)Tt * Kk * Pp]; // [t][k][p]
__device__ __align__(16) __nv_bfloat16 g_XtL[(size_t)Tt * Kk * Pp];
__device__ __align__(16) float         g_XP[(size_t)Tt * Mm * Pp];  // [t][m][p], m=4c+g
__device__ __align__(16) float         g_Hseq[(size_t)Tt * Cc * Pp];// [t][c][p]
__device__ __align__(16) __nv_bfloat16 g_WxH[Mm * Kk], g_WxL[Mm * Kk]; // rows m=4c+g
__device__ __align__(16) __nv_bfloat16 g_WhH[Mm * Kk], g_WhL[Mm * Kk];
__device__ __align__(16) __nv_bfloat16 g_HH[2][Kk * Pp], g_HL[2][Kk * Pp]; // H: [k][p]
__device__ __align__(16) float         g_Cell[Cc * Pp];
__device__ unsigned g_barrier_cnt;

// ------------ cp.async helpers ------------
__device__ __forceinline__ void cp16(void* dst, const void* src) {
    unsigned int d = (unsigned int)__cvta_generic_to_shared(dst);
    asm volatile("cp.async.cg.shared.global [%0], [%1], 16;\n" :: "r"(d), "l"(src));
}
#define CP_COMMIT() asm volatile("cp.async.commit_group;\n" ::)
#define CP_WAIT1()  asm volatile("cp.async.wait_group 1;\n" ::)
#define CP_WAIT0()  asm volatile("cp.async.wait_group 0;\n" ::)

__device__ __forceinline__ void bf16_split(float v, __nv_bfloat16& h, __nv_bfloat16& l) {
    h = __float2bfloat16(v);
    l = __float2bfloat16(v - __bfloat162float(h));
}

// monotonic grid barrier: all NBLK_ST CTAs resident by construction
__device__ __forceinline__ void grid_barrier(unsigned target) {
    __syncthreads();
    if (threadIdx.x == 0) {
        __threadfence();                       // publish this CTA's writes
        atomicAdd(&g_barrier_cnt, 1u);
        volatile unsigned* p = &g_barrier_cnt;
        while (*p < target) { }
        __threadfence();                       // acquire other CTAs' writes
    }
    __syncthreads();
}

// ------------ setup kernels ------------
__global__ void init_state() {
    int i = blockIdx.x * blockDim.x + threadIdx.x;
    if (i == 0) g_barrier_cnt = 0;             // reset for every graph replay
    if (i < Kk * Pp) {
        __nv_bfloat16 z = __float2bfloat16(0.f);
        g_HH[0][i] = z; g_HH[1][i] = z;
        g_HL[0][i] = z; g_HL[1][i] = z;
        g_Cell[i] = 0.f;
    }
}

__global__ void split_weights(const float* __restrict__ Wx, const float* __restrict__ Wh) {
    int idx = blockIdx.x * blockDim.x + threadIdx.x;
    if (idx >= 4 * Cc * Cc) return;
    int g = idx >> 18;
    int rem = idx & ((1 << 18) - 1);
    int c = rem >> 9;
    int k = rem & 511;
    int m = (c << 2) | g;
    __nv_bfloat16 h, l;
    bf16_split(Wx[idx], h, l);
    g_WxH[m * Kk + k] = h; g_WxL[m * Kk + k] = l;
    bf16_split(Wh[idx], h, l);
    g_WhH[m * Kk + k] = h; g_WhL[m * Kk + k] = l;
}

// x (B,C,N,T) -> Xt hi/lo [t][c][b*N+n]
__global__ void transpose_split_x(const float* __restrict__ x) {
    __shared__ float tile[32][33];
    int bid   = blockIdx.x;
    int ntile = bid & 7;
    int bc    = bid >> 3;
    int c     = bc & (Cc - 1);
    int b     = bc >> 9;
    int tid = threadIdx.x;
    int tr = tid >> 5, tc = tid & 31;
    const float* src = x + ((size_t)(b * Cc + c) * Nn + ntile * 32) * Tt;
#pragma unroll
    for (int r0 = 0; r0 < 32; r0 += 8)
        tile[r0 + tr][tc] = src[(size_t)(r0 + tr) * Tt + tc];
    __syncthreads();
#pragma unroll
    for (int r0 = 0; r0 < 32; r0 += 8) {
        int t = r0 + tr;
        float v = tile[tc][t];
        __nv_bfloat16 h, l;
        bf16_split(v, h, l);
        size_t o = ((size_t)t * Kk + c) * Pp + b * Nn + ntile * 32 + tc;
        g_XtH[o] = h; g_XtL[o] = l;
    }
}

// g_Hseq[t][c][b*N+n] -> out (B,C,N,T)
__global__ void transpose_out(float* __restrict__ out) {
    __shared__ float tile[32][33];
    int bid   = blockIdx.x;
    int ntile = bid & 7;
    int bc    = bid >> 3;
    int c     = bc & (Cc - 1);
    int b     = bc >> 9;
    int tid = threadIdx.x;
    int tr = tid >> 5, tc = tid & 31;
#pragma unroll
    for (int r0 = 0; r0 < 32; r0 += 8) {
        int t = r0 + tr;
        tile[tc][t] = g_Hseq[((size_t)t * Cc + c) * Pp + b * Nn + ntile * 32 + tc];
    }
    __syncthreads();
    float* dst = out + ((size_t)(b * Cc + c) * Nn + ntile * 32) * Tt;
#pragma unroll
    for (int r0 = 0; r0 < 32; r0 += 8) {
        int n = r0 + tr;
        dst[(size_t)n * Tt + tc] = tile[n][tc];
    }
}

// =========== CORE A: 128 thr, 2x2 warps, 64x64 tiles, 3-stage (for xp_gemm) ===========
struct AccXP {
    wmma::fragment<wmma::accumulator, 16, 16, 16, float> a[4][4];
};

__device__ __forceinline__ void gemm_core_xp(
    const __nv_bfloat16* __restrict__ AH, const __nv_bfloat16* __restrict__ AL,
    const __nv_bfloat16* __restrict__ BH, const __nv_bfloat16* __restrict__ BL,
    __nv_bfloat16* sm, int tid, int wm, int wn, AccXP& acc)
{
#pragma unroll
    for (int i = 0; i < 4; i++)
#pragma unroll
        for (int j = 0; j < 4; j++) wmma::fill_fragment(acc.a[i][j], 0.f);

    auto load_tiles = [&](int buf, int k0) {
        __nv_bfloat16* base = sm + buf * BUF_ELEMS;
        __nv_bfloat16* asH = base;
        __nv_bfloat16* asL = base + SZ_A;
        __nv_bfloat16* bsH = base + 2 * SZ_A;
        __nv_bfloat16* bsL = base + 2 * SZ_A + SZ_B;
#pragma unroll
        for (int it = 0; it < 4; ++it) {
            int idx = tid + it * 128;
            int row = idx >> 2, q = idx & 3;
            cp16(asH + row * LDA + q * 8, AH + (size_t)row * Kk + k0 + q * 8);
            cp16(asL + row * LDA + q * 8, AL + (size_t)row * Kk + k0 + q * 8);
        }
#pragma unroll
        for (int it = 0; it < 4; ++it) {
            int idx = tid + it * 128;
            int kk = idx >> 4, q = idx & 15;
            cp16(bsH + kk * LDB + q * 8, BH + (size_t)(k0 + kk) * Pp + q * 8);
            cp16(bsL + kk * LDB + q * 8, BL + (size_t)(k0 + kk) * Pp + q * 8);
        }
        CP_COMMIT();
    };

    auto compute = [&](int buf) {
        __nv_bfloat16* base = sm + buf * BUF_ELEMS;
        __nv_bfloat16* asH = base;
        __nv_bfloat16* asL = base + SZ_A;
        __nv_bfloat16* bsH = base + 2 * SZ_A;
        __nv_bfloat16* bsL = base + 2 * SZ_A + SZ_B;
#pragma unroll
        for (int kk = 0; kk < BK; kk += 16) {
            wmma::fragment<wmma::matrix_a, 16, 16, 16, __nv_bfloat16, wmma::row_major> ah[4], al[4];
#pragma unroll
            for (int i = 0; i < 4; i++) {
                wmma::load_matrix_sync(ah[i], asH + (wm * 64 + i * 16) * LDA + kk, LDA);
                wmma::load_matrix_sync(al[i], asL + (wm * 64 + i * 16) * LDA + kk, LDA);
            }
#pragma unroll
            for (int j = 0; j < 4; j++) {
                wmma::fragment<wmma::matrix_b, 16, 16, 16, __nv_bfloat16, wmma::row_major> bh, bl;
                wmma::load_matrix_sync(bh, bsH + kk * LDB + wn * 64 + j * 16, LDB);
                wmma::load_matrix_sync(bl, bsL + kk * LDB + wn * 64 + j * 16, LDB);
#pragma unroll
                for (int i = 0; i < 4; i++) wmma::mma_sync(acc.a[i][j], ah[i], bh, acc.a[i][j]);
#pragma unroll
                for (int i = 0; i < 4; i++) wmma::mma_sync(acc.a[i][j], al[i], bh, acc.a[i][j]);
#pragma unroll
                for (int i = 0; i < 4; i++) wmma::mma_sync(acc.a[i][j], ah[i], bl, acc.a[i][j]);
            }
        }
    };

    load_tiles(0, 0);
    load_tiles(1, BK);
#pragma unroll 1
    for (int i = 0; i < NKIT; ++i) {
        asm volatile("cp.async.wait_group 1;\n" ::);
        __syncthreads();
        if (i + 2 < NKIT) load_tiles((i + 2) % 3, (i + 2) * BK);
        compute(i % 3);
    }
}

__global__ __launch_bounds__(128, 2) void xp_gemm() {
    extern __shared__ char smraw[];
    __nv_bfloat16* sm = reinterpret_cast<__nv_bfloat16*>(smraw);

    int m0 = blockIdx.x * BM;          // fast dim: m-tiles share B tile via L2
    int colTile = blockIdx.y;
    int t  = colTile >> 4;
    int p0 = (colTile & 15) * BN;

    int tid    = threadIdx.x;
    int warpId = tid >> 5;
    int wm = warpId & 1;
    int wn = warpId >> 1;

    AccXP acc;
    gemm_core_xp(g_WxH + (size_t)m0 * Kk, g_WxL + (size_t)m0 * Kk,
                 g_XtH + (size_t)t * Kk * Pp + p0, g_XtL + (size_t)t * Kk * Pp + p0,
                 sm, tid, wm, wn, acc);

    float* XPbase = g_XP + (size_t)t * Mm * Pp + (size_t)m0 * Pp + p0;
#pragma unroll
    for (int i = 0; i < 4; i++)
#pragma unroll
        for (int j = 0; j < 4; j++)
            wmma::store_matrix_sync(XPbase + (size_t)(wm * 64 + i * 16) * Pp + wn * 64 + j * 16,
                                    acc.a[i][j], Pp, wmma::mem_row_major);
}

// =========== persistent step kernel: core B, 32 steps, grid barrier ===========
struct AccST {
    wmma::fragment<wmma::accumulator, 16, 16, 16, float> a[2][4];
};

__global__ __launch_bounds__(256, 2) void lstm_persist(const float* __restrict__ bx,
                                                       const float* __restrict__ bh) {
    extern __shared__ char smraw[];
    __nv_bfloat16* sm = reinterpret_cast<__nv_bfloat16*>(smraw);
    float* Zs = reinterpret_cast<float*>(smraw);   // alias, used after final GEMM sync

    int p0 = (blockIdx.x & 15) * BN;
    int m0 = (blockIdx.x >> 4) * BM;

    int tid    = threadIdx.x;
    int warpId = tid >> 5;
    int wm = warpId & 3;
    int wn = warpId >> 2;

    const __nv_bfloat16* AH = g_WhH + (size_t)m0 * Kk;
    const __nv_bfloat16* AL = g_WhL + (size_t)m0 * Kk;

    // per-thread epilogue biases (c fixed per (tid,it) pair across steps)
    float biasv[16][4];
#pragma unroll
    for (int it = 0; it < 16; it++) {
        int idx = tid + it * 256;
        int cl = idx >> 7;
        int c = (m0 >> 2) + cl;
        biasv[it][0] = bx[c] + bh[c];
        biasv[it][1] = bx[Cc + c] + bh[Cc + c];
        biasv[it][2] = bx[2 * Cc + c] + bh[2 * Cc + c];
        biasv[it][3] = bx[3 * Cc + c] + bh[3 * Cc + c];
    }

#pragma unroll 1
    for (int t = 0; t < Tt; ++t) {
        const __nv_bfloat16* BH = g_HH[t & 1] + p0;
        const __nv_bfloat16* BL = g_HL[t & 1] + p0;

        AccST acc;
        {
            const float* XPbase = g_XP + (size_t)t * Mm * Pp + (size_t)m0 * Pp + p0;
#pragma unroll
            for (int i = 0; i < 2; i++)
#pragma unroll
                for (int j = 0; j < 4; j++)
                    wmma::load_matrix_sync(acc.a[i][j],
                        XPbase + (size_t)(wm * 32 + i * 16) * Pp + wn * 64 + j * 16,
                        Pp, wmma::mem_row_major);
        }

        auto load_tiles = [&](int buf, int k0) {
            __nv_bfloat16* base = sm + buf * BUF_ELEMS;
            __nv_bfloat16* asH = base;
            __nv_bfloat16* asL = base + SZ_A;
            __nv_bfloat16* bsH = base + 2 * SZ_A;
            __nv_bfloat16* bsL = base + 2 * SZ_A + SZ_B;
#pragma unroll
            for (int it = 0; it < 2; ++it) {
                int idx = tid + it * 256;
                int row = idx >> 2, q = idx & 3;
                cp16(asH + row * LDA + q * 8, AH + (size_t)row * Kk + k0 + q * 8);
                cp16(asL + row * LDA + q * 8, AL + (size_t)row * Kk + k0 + q * 8);
            }
#pragma unroll
            for (int it = 0; it < 2; ++it) {
                int idx = tid + it * 256;
                int kk = idx >> 4, q = idx & 15;
                cp16(bsH + kk * LDB + q * 8, BH + (size_t)(k0 + kk) * Pp + q * 8);
                cp16(bsL + kk * LDB + q * 8, BL + (size_t)(k0 + kk) * Pp + q * 8);
            }
            CP_COMMIT();
        };

        auto compute = [&](int buf) {
            __nv_bfloat16* base = sm + buf * BUF_ELEMS;
            __nv_bfloat16* asH = base;
            __nv_bfloat16* asL = base + SZ_A;
            __nv_bfloat16* bsH = base + 2 * SZ_A;
            __nv_bfloat16* bsL = base + 2 * SZ_A + SZ_B;
#pragma unroll
            for (int kk = 0; kk < BK; kk += 16) {
                wmma::fragment<wmma::matrix_a, 16, 16, 16, __nv_bfloat16, wmma::row_major> ah[2], al[2];
#pragma unroll
                for (int i = 0; i < 2; i++) {
                    wmma::load_matrix_sync(ah[i], asH + (wm * 32 + i * 16) * LDA + kk, LDA);
                    wmma::load_matrix_sync(al[i], asL + (wm * 32 + i * 16) * LDA + kk, LDA);
                }
#pragma unroll
                for (int j = 0; j < 4; j++) {
                    wmma::fragment<wmma::matrix_b, 16, 16, 16, __nv_bfloat16, wmma::row_major> bh2, bl2;
                    wmma::load_matrix_sync(bh2, bsH + kk * LDB + wn * 64 + j * 16, LDB);
                    wmma::load_matrix_sync(bl2, bsL + kk * LDB + wn * 64 + j * 16, LDB);
#pragma unroll
                    for (int i = 0; i < 2; i++) {
                        wmma::mma_sync(acc.a[i][j], ah[i], bh2, acc.a[i][j]);
                        wmma::mma_sync(acc.a[i][j], al[i], bh2, acc.a[i][j]);
                        wmma::mma_sync(acc.a[i][j], ah[i], bl2, acc.a[i][j]);
                    }
                }
            }
        };

        load_tiles(0, 0);
#pragma unroll 1
        for (int i = 0; i < NKIT; ++i) {
            if (i + 1 < NKIT) { load_tiles((i + 1) & 1, (i + 1) * BK); CP_WAIT1(); }
            else              { CP_WAIT0(); }
            __syncthreads();
            compute(i & 1);
            __syncthreads();
        }

#pragma unroll
        for (int i = 0; i < 2; i++)
#pragma unroll
            for (int j = 0; j < 4; j++)
                wmma::store_matrix_sync(Zs + (wm * 32 + i * 16) * LDZ + wn * 64 + j * 16,
                                        acc.a[i][j], LDZ, wmma::mem_row_major);
        __syncthreads();

        __nv_bfloat16* HoutH = g_HH[(t + 1) & 1];
        __nv_bfloat16* HoutL = g_HL[(t + 1) & 1];
#pragma unroll
        for (int it = 0; it < 16; it++) {
            int idx = tid + it * 256;
            int cl = idx >> 7;
            int pl = idx & 127;
            int c = (m0 >> 2) + cl;
            int p = p0 + pl;

            float zi = Zs[(4 * cl + 0) * LDZ + pl] + biasv[it][0];
            float zf = Zs[(4 * cl + 1) * LDZ + pl] + biasv[it][1];
            float zo = Zs[(4 * cl + 2) * LDZ + pl] + biasv[it][2];
            float zg = Zs[(4 * cl + 3) * LDZ + pl] + biasv[it][3];

            float ig = 1.f / (1.f + __expf(-zi));
            float fg = 1.f / (1.f + __expf(-zf));
            float og = 1.f / (1.f + __expf(-zo));
            float gg = tanhf(zg);

            float cp = g_Cell[c * Pp + p];
            float cn = fg * cp + ig * gg;
            g_Cell[c * Pp + p] = cn;
            float h = og * tanhf(cn);

            __nv_bfloat16 hh, hl;
            bf16_split(h, hh, hl);
            HoutH[c * Pp + p] = hh;
            HoutL[c * Pp + p] = hl;

            g_Hseq[((size_t)t * Cc + c) * Pp + p] = h;
        }

        grid_barrier((unsigned)NBLK_ST * (t + 1));
    }
}

extern "C" void kernel_launch(void* const* d_in, const int* in_sizes, int n_in,
                              void* d_out, int out_size) {
    const float* x  = (const float*)d_in[0];
    const float* Wx = (const float*)d_in[1];
    const float* bx = (const float*)d_in[2];
    const float* Wh = (const float*)d_in[3];
    const float* bh = (const float*)d_in[4];
    float* out = (float*)d_out;

    cudaFuncSetAttribute(xp_gemm,      cudaFuncAttributeMaxDynamicSharedMemorySize, SMEM_XP);
    cudaFuncSetAttribute(lstm_persist, cudaFuncAttributeMaxDynamicSharedMemorySize, SMEM_ST);

    init_state<<<(Kk * Pp + 255) / 256, 256>>>();
    split_weights<<<(4 * Cc * Cc + 255) / 256, 256>>>(Wx, Wh);
    transpose_split_x<<<Bb * Cc * (Nn / 32), 256>>>(x);
    xp_gemm<<<dim3(16, 512), 128, SMEM_XP>>>();
    lstm_persist<<<NBLK_ST, 256, SMEM_ST>>>(bx, bh);
    transpose_out<<<Bb * Cc * (Nn / 32), 256>>>(out);
}